// round 16
// baseline (speedup 1.0000x reference)
#include <cuda_runtime.h>
#include <stdint.h>

// ---------------- Problem constants ----------------
#define BSZ    16384
#define DIM    256
#define NHARD  3276                       // int(16384*0.2)
#define NCHUNK 16
#define JCHUNK (BSZ / NCHUNK)             // 1024
#define ITILE  16
#define NITILE ((NHARD + ITILE - 1) / ITILE)  // 205

// ---------------- Scratch (__device__ globals; no allocations allowed) ----
__device__ float g_znT[DIM * BSZ];        // z-normalized, transposed [k][j]
__device__ int   g_src[NHARD];
__device__ float g_alpha[NHARD];
__device__ float g_pval[NHARD * NCHUNK];
__device__ int   g_pj[NHARD * NCHUNK];
__device__ int   g_tgt[NHARD];

// ---------------- threefry2x32 (JAX-compatible, 20 rounds) ----------------
__host__ __device__ __forceinline__ void tf2x32(uint32_t k0, uint32_t k1,
                                                uint32_t x0, uint32_t x1,
                                                uint32_t* o0, uint32_t* o1) {
    uint32_t ks0 = k0, ks1 = k1, ks2 = k0 ^ k1 ^ 0x1BD11BDAu;
    x0 += ks0; x1 += ks1;
#define TFR(r) { x0 += x1; x1 = (x1 << (r)) | (x1 >> (32 - (r))); x1 ^= x0; }
    TFR(13) TFR(15) TFR(26) TFR(6)   x0 += ks1; x1 += ks2 + 1u;
    TFR(17) TFR(29) TFR(16) TFR(24)  x0 += ks2; x1 += ks0 + 2u;
    TFR(13) TFR(15) TFR(26) TFR(6)   x0 += ks0; x1 += ks1 + 3u;
    TFR(17) TFR(29) TFR(16) TFR(24)  x0 += ks1; x1 += ks2 + 4u;
    TFR(13) TFR(15) TFR(26) TFR(6)   x0 += ks2; x1 += ks0 + 5u;
#undef TFR
    *o0 = x0; *o1 = x1;
}

// partitionable 32-bit random word at flat counter p: xor of both outputs [VALIDATED]
__device__ __forceinline__ uint32_t rng_word32(uint32_t k0, uint32_t k1, uint32_t p) {
    uint32_t a, b;
    tf2x32(k0, k1, 0u, p, &a, &b);
    return a ^ b;
}

// ---------------- accurate logf (cephes; matches Eigen/XLA plog ~1ulp) ----
__device__ __forceinline__ float log_cephes(float x) {
    int ix = __float_as_int(x);
    int e = ((ix >> 23) & 0xff) - 126;                     // mantissa in [0.5,1)
    float m = __int_as_float((ix & 0x007fffff) | 0x3f000000);
    if (m < 0.707106781186547524f) { e -= 1; m = m + m - 1.0f; }
    else                           { m = m - 1.0f; }
    float z = m * m;
    float p = 7.0376836292e-2f;
    p = fmaf(p, m, -1.1514610310e-1f);
    p = fmaf(p, m,  1.1676998740e-1f);
    p = fmaf(p, m, -1.2420140846e-1f);
    p = fmaf(p, m,  1.4249322787e-1f);
    p = fmaf(p, m, -1.6668057665e-1f);
    p = fmaf(p, m,  2.0000714765e-1f);
    p = fmaf(p, m, -2.4999993993e-1f);
    p = fmaf(p, m,  3.3333331174e-1f);
    float y = m * z * p;
    float fe = (float)e;
    y = fmaf(fe, -2.12194440e-4f, y);
    y = y - 0.5f * z;
    y = m + y;
    y = fmaf(fe, 0.693359375f, y);
    return y;
}

__device__ __forceinline__ float gumbel_from_word(uint32_t w) {
    float f = __uint_as_float((w >> 9) | 0x3f800000u) - 1.0f;
    float u = f + 1.17549435e-38f;     // minval=tiny clamp
    float t = -log_cephes(u);
    return -log_cephes(t);
}

// ---------------- K1: row-normalize + transpose ----------------
__global__ void norm_kernel(const float* __restrict__ z) {
    int row = blockIdx.x;
    int tid = threadIdx.x;
    float v = z[row * DIM + tid];
    float s = v * v;
#pragma unroll
    for (int off = 16; off; off >>= 1) s += __shfl_xor_sync(0xffffffffu, s, off);
    __shared__ float ws[8];
    if ((tid & 31) == 0) ws[tid >> 5] = s;
    __syncthreads();
    float tot = 0.f;
#pragma unroll
    for (int w = 0; w < 8; w++) tot += ws[w];
    float nrm = fmaxf(__fsqrt_rn(tot), 1e-12f);
    g_znT[tid * BSZ + row] = __fdiv_rn(v, nrm);
}

// ---------------- K2: src_idx + alpha ----------------
// randint SPLITS its key: k1,k2 = split(k_src); lower_bits = random_bits(k2, 32, (n,))
// span 2^14 -> multiplier 0 -> src = lower_bits & 16383, counters 0..n-1.
// (l20,l21) = k2 = tf(k_src,(0,1)) computed on host.
__global__ void rng_kernel(uint32_t l20, uint32_t l21, uint32_t a0, uint32_t a1) {
    int i = blockIdx.x * blockDim.x + threadIdx.x;
    if (i >= NHARD) return;
    uint32_t w = rng_word32(l20, l21, (uint32_t)i);
    g_src[i] = (int)(w & (BSZ - 1));
    // alpha: uniform does NOT split; direct key, xor rule, counter i
    uint32_t wa = rng_word32(a0, a1, (uint32_t)i);
    float f = __uint_as_float((wa >> 9) | 0x3f800000u) - 1.0f;
    g_alpha[i] = 0.5f * f;
}

// ---------------- K3: fused dot + gumbel + blockwise argmax ----------------
__global__ void __launch_bounds__(256, 2) score_kernel(uint32_t kt0, uint32_t kt1) {
    __shared__ float Qs[DIM][ITILE];      // 16 KB [k][ii]
    __shared__ int   sSrc[ITILE];
    __shared__ float wV[ITILE][8];
    __shared__ int   wJ[ITILE][8];

    int tid = threadIdx.x;
    int chunk = blockIdx.x, itile = blockIdx.y;

    if (tid < ITILE) {
        int ih = itile * ITILE + tid;
        sSrc[tid] = (ih < NHARD) ? g_src[ih] : -1;
    }
    __syncthreads();
#pragma unroll
    for (int ii = 0; ii < ITILE; ii++) {
        int s = sSrc[ii];
        Qs[tid][ii] = (s >= 0) ? g_znT[tid * BSZ + s] : 0.f;
    }
    __syncthreads();

    int j0 = chunk * JCHUNK + tid * 4;
    float4 acc[ITILE];
#pragma unroll
    for (int ii = 0; ii < ITILE; ii++) acc[ii] = make_float4(0.f, 0.f, 0.f, 0.f);

    const float4* zt4 = (const float4*)g_znT;
#pragma unroll 2
    for (int k = 0; k < DIM; k++) {
        float4 v = __ldg(&zt4[(k * BSZ + j0) >> 2]);
        float q[16];
        *(float4*)&q[0]  = *(const float4*)&Qs[k][0];
        *(float4*)&q[4]  = *(const float4*)&Qs[k][4];
        *(float4*)&q[8]  = *(const float4*)&Qs[k][8];
        *(float4*)&q[12] = *(const float4*)&Qs[k][12];
#pragma unroll
        for (int ii = 0; ii < 16; ii++) {
            acc[ii].x = fmaf(q[ii], v.x, acc[ii].x);
            acc[ii].y = fmaf(q[ii], v.y, acc[ii].y);
            acc[ii].z = fmaf(q[ii], v.z, acc[ii].z);
            acc[ii].w = fmaf(q[ii], v.w, acc[ii].w);
        }
    }

    int lane = tid & 31, warp = tid >> 5;
    const float NEGINF = __int_as_float(0xff800000);
#pragma unroll 1
    for (int ii = 0; ii < ITILE; ii++) {
        int ih = itile * ITILE + ii;
        float bv = NEGINF; int bj = -1;
        if (ih < NHARD) {
            int srcv = sSrc[ii];
            float d[4] = {acc[ii].x, acc[ii].y, acc[ii].z, acc[ii].w};
#pragma unroll
            for (int t = 0; t < 4; t++) {
                int j = j0 + t;
                uint32_t ctr = ((uint32_t)ih << 14) | (uint32_t)j;   // ih*16384 + j
                uint32_t w = rng_word32(kt0, kt1, ctr);
                float g = gumbel_from_word(w);
                float sc = __fdiv_rn(d[t], 0.1f) + g;
                if (j == srcv) sc = NEGINF;                          // diagonal
                if (sc > bv) { bv = sc; bj = j; }                    // first max
            }
        }
#pragma unroll
        for (int off = 16; off; off >>= 1) {
            float ov = __shfl_down_sync(0xffffffffu, bv, off);
            int   oj = __shfl_down_sync(0xffffffffu, bj, off);
            if (ov > bv || (ov == bv && (unsigned)oj < (unsigned)bj)) { bv = ov; bj = oj; }
        }
        if (lane == 0) { wV[ii][warp] = bv; wJ[ii][warp] = bj; }
    }
    __syncthreads();

    if (tid < ITILE) {
        float bv = wV[tid][0]; int bj = wJ[tid][0];
#pragma unroll
        for (int w = 1; w < 8; w++) {
            float ov = wV[tid][w]; int oj = wJ[tid][w];
            if (ov > bv || (ov == bv && (unsigned)oj < (unsigned)bj)) { bv = ov; bj = oj; }
        }
        int ih = itile * ITILE + tid;
        if (ih < NHARD) { g_pval[ih * NCHUNK + chunk] = bv; g_pj[ih * NCHUNK + chunk] = bj; }
    }
}

// ---------------- K4: reduce chunk partials -> tgt_idx ----------------
__global__ void reduce_kernel() {
    int i = blockIdx.x * blockDim.x + threadIdx.x;
    if (i >= NHARD) return;
    float bv = g_pval[i * NCHUNK]; int bj = g_pj[i * NCHUNK];
#pragma unroll
    for (int c = 1; c < NCHUNK; c++) {
        float v = g_pval[i * NCHUNK + c]; int j = g_pj[i * NCHUNK + c];
        if (v > bv || (v == bv && (unsigned)j < (unsigned)bj)) { bv = v; bj = j; }
    }
    g_tgt[i] = bj;
}

// ---------------- K5: mix hard negatives ----------------
__global__ void mix_kernel(const float* __restrict__ z, float* __restrict__ out) {
    int i = blockIdx.x, d = threadIdx.x;
    float a = g_alpha[i];
    float zs = z[g_src[i] * DIM + d];
    float zt = z[g_tgt[i] * DIM + d];
    out[i * DIM + d] = a * zs + (1.0f - a) * zt;
}

// ---------------- launch ----------------
extern "C" void kernel_launch(void* const* d_in, const int* in_sizes, int n_in,
                              void* d_out, int out_size) {
    const float* z = (const float*)d_in[0];
    float* out = (float*)d_out;

    // foldlike split(key(42),3): child_i = BOTH outputs of tf((0,42),(0,i))  [VALIDATED]
    uint32_t r00, r01, r10, r11, r20, r21;
    tf2x32(0u, 42u, 0u, 0u, &r00, &r01);   // k_src
    tf2x32(0u, 42u, 0u, 1u, &r10, &r11);   // k_tgt (categorical; validated)
    tf2x32(0u, 42u, 0u, 2u, &r20, &r21);   // k_alpha

    // randint's INTERNAL split: k1,k2 = split(k_src); lower_bits uses k2
    uint32_t l20, l21;
    tf2x32(r00, r01, 0u, 1u, &l20, &l21);  // k2 = child1 of split(k_src)

    norm_kernel<<<BSZ, DIM>>>(z);
    rng_kernel<<<(NHARD + 255) / 256, 256>>>(l20, l21, r20, r21);
    score_kernel<<<dim3(NCHUNK, NITILE), 256>>>(r10, r11);
    reduce_kernel<<<(NHARD + 255) / 256, 256>>>();
    mix_kernel<<<NHARD, DIM>>>(z, out);
}